// round 8
// baseline (speedup 1.0000x reference)
#include <cuda_runtime.h>
#include <cstdint>

// Soft Smith-Waterman, linear (exp) domain, 8x8 row-blocked wavefront,
// PER-LANE exponent renormalization.
// X = exp(H):  X = 1 + e^s * Xdiag + e^-1 * (Xup + Xleft)
// Each lane carries Y = X * 2^-Ki with its OWN Ki, renormed every 4 steps.
// Cross-lane / cross-band exchanges rescale by 2^(Ksrc - Kdst) (always small
// since neighbors are only ~8-32 rows apart).
// Lane l owns 8 cols; computes 8 rows x 8 cols per step; stagger 1 step/lane.
// Bands of 256 cols, 8 bands x 8 batches = 64 warps. Scores pre-exponentiated
// into a staircase layout by a full-chip prepass.

#define MM 2048
#define NN 2048
#define RB 8
#define CL 8
#define BANDW 256
#define NB 8
#define NSTEP 287
#define SPAD 288
#define LN2 0.6931471805599453f
#define EG  0.36787944117144233f    // e^-1

__device__ float4 g_ex[8][NB][SPAD][32][16];   // staircase exp-scores
__device__ float2 g_edge2[8][NB][MM];          // (Y, K-bits) per edge row
__device__ int    g_flag[8][NB];
__device__ int    g_max[8];

static __device__ __forceinline__ float lg2f(float x) {
    float r; asm("lg2.approx.f32 %0, %1;" : "=f"(r) : "f"(x)); return r;
}
static __device__ __forceinline__ int ld_acq(const int* p) {
    int v; asm volatile("ld.global.acquire.gpu.b32 %0, [%1];" : "=r"(v) : "l"(p)); return v;
}
static __device__ __forceinline__ void st_rel(int* p, int v) {
    asm volatile("st.global.release.gpu.b32 [%0], %1;" :: "l"(p), "r"(v) : "memory");
}
static __device__ __forceinline__ float pow2i(int k) {   // 2^k, k in [-126,127]
    return __int_as_float((127 + k) << 23);
}

#define COMP(v4, k) ((k)==0 ? (v4).x : (k)==1 ? (v4).y : (k)==2 ? (v4).z : (v4).w)

// ---------- Prepass: exp + staircase layout ----------
__global__ void sw_exp_kernel(const float* __restrict__ S) {
    long long i = (long long)blockIdx.x * 256 + threadIdx.x;   // 9,437,184
    int q  = (int)(i & 15);
    int l  = (int)((i >> 4) & 31);
    long long rest = i >> 9;
    int s  = (int)(rest % SPAD);
    int bw = (int)(rest / SPAD);
    int w  = bw & (NB - 1), b = bw >> 3;
    int rr = q >> 1, h = q & 1;
    int r  = RB * (s - l) + rr;
    float4 v = make_float4(0.f, 0.f, 0.f, 0.f);
    if (r >= 0 && r < MM) {
        float4 sc4 = __ldg((const float4*)(S + ((size_t)b * MM + r) * NN
                                           + w * BANDW + l * CL + h * 4));
        v.x = __expf(sc4.x); v.y = __expf(sc4.y);
        v.z = __expf(sc4.z); v.w = __expf(sc4.w);
    }
    g_ex[b][w][s][l][q] = v;
}

__global__ void sw_init_kernel() {
    int i = threadIdx.x;
    if (i < 8 * NB) ((int*)g_flag)[i] = 0;
    if (i < 8) g_max[i] = 0;    // bits of 0.0f; H >= 0
}

// ---------- Wave kernel ----------
__global__ void __launch_bounds__(32, 1) sw_wave_kernel() {
    const int b = blockIdx.y;
    const int w = blockIdx.x;
    const int l = threadIdx.x;

    const float4* exbase = &g_ex[b][w][0][l][0];      // step stride = 512 float4
    const int*    flagp   = (w > 0) ? &g_flag[b][w - 1] : (const int*)0;
    const float2* edge2p  = (w > 0) ? g_edge2[b][w - 1] : (const float2*)0;
    float2*       myedge2 = g_edge2[b][w];
    int*          myflag  = &g_flag[b][w];
    const bool    produce = (w != NB - 1);

    float B[8], yR[8];
    #pragma unroll
    for (int j = 0; j < 8; ++j) { B[j] = 1.f; yR[j] = 1.f; }
    float y7p = 1.f, ecarry = 1.f, C = 1.f;
    float Ymax = 0.f, vh = 0.f;
    int   Ki = 0;                    // PER-LANE exponent
    float4 rq[4] = {};
    int   flag_seen = 0, f_pend = 0;
    bool  have_raw = false;

    float4 bufA[16], bufB[16];
    #pragma unroll
    for (int q = 0; q < 16; ++q) bufA[q] = __ldcg(exbase + q);

    if (w > 0) { while (flag_seen < 4) flag_seen = ld_acq(flagp); }

#define STEP(CUR, NXT, SS) { \
    const int s_ = (SS); \
    /* per-lane renorm every 4 steps (32 rows) */ \
    if ((s_ & 3) == 0 && s_ != 0) { \
        float m_ = B[0]; \
        _Pragma("unroll") for (int j = 1; j < 8; ++j) m_ = fmaxf(m_, B[j]); \
        int k_ = (__float_as_int(m_) >> 23) - 127;   /* m_ > 0 always */ \
        float sc_ = pow2i(-k_); \
        vh = fmaxf(vh, lg2f(Ymax) + (float)Ki); \
        Ymax = 0.f; Ki += k_; C *= sc_; \
        _Pragma("unroll") for (int j = 0; j < 8; ++j) { B[j] *= sc_; yR[j] *= sc_; } \
        y7p *= sc_; ecarry *= sc_; \
    } \
    /* prefetch next step's scores (slot NSTEP reads zero-padded SPAD slot) */ \
    { const float4* p_ = exbase + (size_t)(s_ + 1) * 512; \
      _Pragma("unroll") for (int q = 0; q < 16; ++q) NXT[q] = __ldcg(p_ + q); } \
    /* edge intake (meaningful on lane 0; uniform execution) */ \
    float e_[8]; \
    if (w > 0 && s_ < 256) { \
        flag_seen = max(flag_seen, f_pend); \
        if (!have_raw) { \
            while (flag_seen < s_ + 1) flag_seen = ld_acq(flagp); \
            const float4* ep_ = (const float4*)(edge2p + RB * s_); \
            rq[0] = __ldcg(ep_); rq[1] = __ldcg(ep_ + 1); \
            rq[2] = __ldcg(ep_ + 2); rq[3] = __ldcg(ep_ + 3); \
        } \
        _Pragma("unroll") for (int t = 0; t < 4; ++t) { \
            int k0 = max(-126, min(127, __float_as_int(rq[t].y) - Ki)); \
            int k1 = max(-126, min(127, __float_as_int(rq[t].w) - Ki)); \
            e_[2 * t]     = rq[t].x * pow2i(k0); \
            e_[2 * t + 1] = rq[t].z * pow2i(k1); \
        } \
        have_raw = false; \
        if (s_ + 1 < 256 && flag_seen >= s_ + 2) { \
            const float4* e2_ = (const float4*)(edge2p + RB * (s_ + 1)); \
            rq[0] = __ldcg(e2_); rq[1] = __ldcg(e2_ + 1); \
            rq[2] = __ldcg(e2_ + 2); rq[3] = __ldcg(e2_ + 3); \
            have_raw = true; \
        } \
        f_pend = ld_acq(flagp); \
    } else { \
        _Pragma("unroll") for (int j = 0; j < 8; ++j) e_[j] = C; \
    } \
    /* neighbor exchange with per-lane rescale: factor 2^(K[l-1] - K[l]) */ \
    int kk_ = __shfl_up_sync(0xffffffffu, Ki, 1); \
    float fs_ = pow2i(max(-126, min(127, kk_ - Ki))); \
    float Lf[8]; float Ld; \
    _Pragma("unroll") for (int j = 0; j < 8; ++j) { \
        float t_ = __shfl_up_sync(0xffffffffu, yR[j], 1); \
        Lf[j] = (l == 0) ? e_[j] : t_ * fs_; \
    } \
    { float t_ = __shfl_up_sync(0xffffffffu, y7p, 1); \
      Ld = (l == 0) ? ecarry : t_ * fs_; } \
    ecarry = e_[7]; \
    const bool valid_ = (s_ >= l) && (s_ - l < 256); \
    const bool z_ = (s_ == l); \
    if (z_) Ld = C; \
    _Pragma("unroll") for (int j = 0; j < 8; ++j) if (z_) B[j] = C; \
    /* 8x8 block: columns left->right, rows top->bottom */ \
    float dc_ = Ld; float ymx_ = 0.f; \
    _Pragma("unroll") for (int cc = 0; cc < 8; ++cc) { \
        float u_ = B[cc]; \
        float v0 = fmaf(EG, Lf[0], fmaf(EG, u_, fmaf(COMP(CUR[0 + (cc >> 2)], cc & 3), dc_,   C))); \
        float v1 = fmaf(EG, Lf[1], fmaf(EG, v0, fmaf(COMP(CUR[2 + (cc >> 2)], cc & 3), Lf[0], C))); \
        float v2 = fmaf(EG, Lf[2], fmaf(EG, v1, fmaf(COMP(CUR[4 + (cc >> 2)], cc & 3), Lf[1], C))); \
        float v3 = fmaf(EG, Lf[3], fmaf(EG, v2, fmaf(COMP(CUR[6 + (cc >> 2)], cc & 3), Lf[2], C))); \
        float v4 = fmaf(EG, Lf[4], fmaf(EG, v3, fmaf(COMP(CUR[8 + (cc >> 2)], cc & 3), Lf[3], C))); \
        float v5 = fmaf(EG, Lf[5], fmaf(EG, v4, fmaf(COMP(CUR[10 + (cc >> 2)], cc & 3), Lf[4], C))); \
        float v6 = fmaf(EG, Lf[6], fmaf(EG, v5, fmaf(COMP(CUR[12 + (cc >> 2)], cc & 3), Lf[5], C))); \
        float v7 = fmaf(EG, Lf[7], fmaf(EG, v6, fmaf(COMP(CUR[14 + (cc >> 2)], cc & 3), Lf[6], C))); \
        dc_ = u_; \
        B[cc] = valid_ ? v7 : u_; \
        ymx_ = fmaxf(ymx_, fmaxf(fmaxf(fmaxf(v0, v1), fmaxf(v2, v3)), \
                                 fmaxf(fmaxf(v4, v5), fmaxf(v6, v7)))); \
        Lf[0] = v0; Lf[1] = v1; Lf[2] = v2; Lf[3] = v3; \
        Lf[4] = v4; Lf[5] = v5; Lf[6] = v6; Lf[7] = v7; \
    } \
    Ymax = fmaxf(Ymax, valid_ ? ymx_ : 0.f); \
    { float t7_ = yR[7]; \
      _Pragma("unroll") for (int j = 0; j < 8; ++j) yR[j] = valid_ ? Lf[j] : yR[j]; \
      y7p = valid_ ? t7_ : y7p; } \
    /* publish right-col rows (lane 31) with own K */ \
    if (l == 31 && produce && valid_) { \
        float kf_ = __int_as_float(Ki); \
        float4* op_ = (float4*)(myedge2 + RB * (s_ - 31)); \
        op_[0] = make_float4(Lf[0], kf_, Lf[1], kf_); \
        op_[1] = make_float4(Lf[2], kf_, Lf[3], kf_); \
        op_[2] = make_float4(Lf[4], kf_, Lf[5], kf_); \
        op_[3] = make_float4(Lf[6], kf_, Lf[7], kf_); \
        st_rel(myflag, s_ - 30); \
    } \
}

    STEP(bufA, bufB, 0)
    for (int s = 1; s + 1 < NSTEP; s += 2) {
        STEP(bufB, bufA, s)
        STEP(bufA, bufB, s + 1)
    }

    // Final flush + warp reduce + publish (H >= 0).
    vh = fmaxf(vh, lg2f(Ymax) + (float)Ki);
    float hv = vh * LN2;
    #pragma unroll
    for (int o = 16; o; o >>= 1)
        hv = fmaxf(hv, __shfl_xor_sync(0xffffffffu, hv, o));
    if (l == 0) atomicMax(&g_max[b], __float_as_int(fmaxf(hv, 0.f)));
#undef STEP
}

__global__ void sw_final_kernel(float* __restrict__ out, int n) {
    int i = threadIdx.x;
    if (i < n) out[i] = __int_as_float(g_max[i]);
}

extern "C" void kernel_launch(void* const* d_in, const int* in_sizes, int n_in,
                              void* d_out, int out_size) {
    (void)n_in; (void)in_sizes;
    const float* S = (const float*)d_in[0];
    float* out = (float*)d_out;
    const int B = out_size;   // 8

    sw_exp_kernel<<<36864, 256>>>(S);
    sw_init_kernel<<<1, 128>>>();
    dim3 grid(NB, 8);
    sw_wave_kernel<<<grid, 32>>>();
    sw_final_kernel<<<1, 32>>>(out, B);
}

// round 9
// speedup vs baseline: 1.0041x; 1.0041x over previous
#include <cuda_runtime.h>
#include <cstdint>

// Soft Smith-Waterman, linear (exp) domain, 8x8 row-blocked wavefront,
// per-lane exponent renorm, smem-staged raw scores (no prepass).
// X = exp(H):  X = 1 + e^s * Xdiag + e^-1 * (Xup + Xleft)
// Lane l owns cols 8l..8l+7 of its band; computes 8 rows x 8 cols per step,
// staggered 1 step per lane. Bands of 256 cols; 8 bands x 8 batches = 64 warps.
// Scores cp.async'd from S into a 4-slot ring, [slot][q][lane] so LDS is
// conflict-free and each lane reads only data it copied.

#define MM 2048
#define NN 2048
#define RB 8
#define BANDW 256
#define NB 8
#define NSTEP 287
#define SLACK 12
#define LN2   0.6931471805599453f
#define LOG2E 1.4426950408889634f
#define EG    0.36787944117144233f    // e^-1

__device__ float2 g_edge2[8][NB][MM];   // (Y, K-bits) per edge row
__device__ int    g_flag[8][NB];
__device__ int    g_max[8];

static __device__ __forceinline__ float ex2f(float x) {
    float r; asm("ex2.approx.f32 %0, %1;" : "=f"(r) : "f"(x)); return r;
}
static __device__ __forceinline__ float lg2f(float x) {
    float r; asm("lg2.approx.f32 %0, %1;" : "=f"(r) : "f"(x)); return r;
}
static __device__ __forceinline__ int ld_acq(const int* p) {
    int v; asm volatile("ld.global.acquire.gpu.b32 %0, [%1];" : "=r"(v) : "l"(p)); return v;
}
static __device__ __forceinline__ void st_rel(int* p, int v) {
    asm volatile("st.global.release.gpu.b32 [%0], %1;" :: "l"(p), "r"(v) : "memory");
}
static __device__ __forceinline__ void cp16(uint32_t dst, const void* src) {
    asm volatile("cp.async.cg.shared.global [%0], [%1], 16;" :: "r"(dst), "l"(src));
}
static __device__ __forceinline__ void cp_commit() {
    asm volatile("cp.async.commit_group;" ::: "memory");
}
template <int N> static __device__ __forceinline__ void cp_wait() {
    asm volatile("cp.async.wait_group %0;" :: "n"(N) : "memory");
}
static __device__ __forceinline__ float pow2i(int k) {   // 2^k, k in [-126,127]
    return __int_as_float((127 + k) << 23);
}

__global__ void sw_init_kernel() {
    int i = threadIdx.x;
    if (i < 8 * NB) ((int*)g_flag)[i] = 0;
    if (i < 8) g_max[i] = 0;    // bits of 0.0f; H >= 0
}

__global__ void __launch_bounds__(32, 1) sw_wave_kernel(const float* __restrict__ S) {
    __shared__ float4 stile[4][16][32];   // 32 KB ring: [slot][q=2*row+half][lane]

    const int b = blockIdx.y;
    const int w = blockIdx.x;
    const int l = threadIdx.x;
    const char* Sl = (const char*)(S + (size_t)b * MM * NN
                                   + (size_t)w * BANDW + (size_t)l * 8);

    const int*    flagp   = (w > 0) ? &g_flag[b][w - 1] : (const int*)0;
    const float2* edge2p  = (w > 0) ? g_edge2[b][w - 1] : (const float2*)0;
    float2*       myedge2 = g_edge2[b][w];
    int*          myflag  = &g_flag[b][w];
    const bool    produce = (w != NB - 1);

    float B[8], yR[8];
    #pragma unroll
    for (int j = 0; j < 8; ++j) { B[j] = 1.f; yR[j] = 1.f; }
    float y7p = 1.f, ecarry = 1.f, C = 1.f;
    float Ymax = 0.f, vh = 0.f;
    int   Ki = 0;
    float4 rq[4] = {};
    int   flag_seen = 0, f_pend = 0;
    bool  have_raw = false;

#define ISSUE_SLOT(SS) { \
    int r0_ = RB * ((SS) - l); \
    r0_ = max(0, min(MM - RB, r0_)); \
    const char* src_ = Sl + (size_t)r0_ * (NN * 4); \
    const int sl_ = (SS) & 3; \
    _Pragma("unroll") for (int rr = 0; rr < 8; ++rr) { \
        uint32_t d0_ = (uint32_t)__cvta_generic_to_shared(&stile[sl_][2 * rr][l]); \
        uint32_t d1_ = (uint32_t)__cvta_generic_to_shared(&stile[sl_][2 * rr + 1][l]); \
        cp16(d0_, src_ + (size_t)rr * (NN * 4)); \
        cp16(d1_, src_ + (size_t)rr * (NN * 4) + 16); \
    } \
    cp_commit(); }

    ISSUE_SLOT(0) ISSUE_SLOT(1) ISSUE_SLOT(2)

    if (w > 0) { while (flag_seen < SLACK) flag_seen = ld_acq(flagp); }

    for (int s = 0; s < NSTEP; ++s) {
        // ---- per-lane renorm every 4 steps (32 rows) ----
        if ((s & 3) == 0 && s != 0) {
            float m_ = B[0];
            #pragma unroll
            for (int j = 1; j < 8; ++j) m_ = fmaxf(m_, B[j]);
            int k_ = (__float_as_int(m_) >> 23) - 127;    // m_ > 0 always
            float sc_ = pow2i(-k_);
            vh = fmaxf(vh, lg2f(Ymax) + (float)Ki);
            Ymax = 0.f; Ki += k_; C *= sc_;
            #pragma unroll
            for (int j = 0; j < 8; ++j) { B[j] *= sc_; yR[j] *= sc_; }
            y7p *= sc_; ecarry *= sc_;
        }

        // ---- score pipeline: issue slot s+3, ensure slot s resident ----
        ISSUE_SLOT(s + 3)
        cp_wait<3>();

        // ---- edge intake (all lanes load same 64 B -> broadcast) ----
        float e_[8];
        if (w > 0 && s < 256) {
            flag_seen = max(flag_seen, f_pend);
            if (!have_raw) {
                while (flag_seen < s + 1) flag_seen = ld_acq(flagp);
                const float4* ep_ = (const float4*)(edge2p + RB * s);
                rq[0] = __ldcg(ep_);     rq[1] = __ldcg(ep_ + 1);
                rq[2] = __ldcg(ep_ + 2); rq[3] = __ldcg(ep_ + 3);
            }
            #pragma unroll
            for (int t = 0; t < 4; ++t) {
                int k0 = max(-126, min(127, __float_as_int(rq[t].y) - Ki));
                int k1 = max(-126, min(127, __float_as_int(rq[t].w) - Ki));
                e_[2 * t]     = rq[t].x * pow2i(k0);
                e_[2 * t + 1] = rq[t].z * pow2i(k1);
            }
            have_raw = false;
            if (s + 1 < 256 && flag_seen >= s + 2) {
                const float4* e2_ = (const float4*)(edge2p + RB * (s + 1));
                rq[0] = __ldcg(e2_);     rq[1] = __ldcg(e2_ + 1);
                rq[2] = __ldcg(e2_ + 2); rq[3] = __ldcg(e2_ + 3);
                have_raw = true;
            }
            f_pend = ld_acq(flagp);
        } else {
            #pragma unroll
            for (int j = 0; j < 8; ++j) e_[j] = C;
        }

        // ---- neighbor exchange with per-lane rescale 2^(K[l-1]-K[l]) ----
        int kk_ = __shfl_up_sync(0xffffffffu, Ki, 1);
        float fs_ = pow2i(max(-126, min(127, kk_ - Ki)));
        float Lf[8]; float Ld;
        #pragma unroll
        for (int j = 0; j < 8; ++j) {
            float t_ = __shfl_up_sync(0xffffffffu, yR[j], 1);
            Lf[j] = (l == 0) ? e_[j] : t_ * fs_;
        }
        { float t_ = __shfl_up_sync(0xffffffffu, y7p, 1);
          Ld = (l == 0) ? ecarry : t_ * fs_; }
        ecarry = e_[7];

        const bool valid_ = (s >= l) && (s - l < 256);
        const bool z_ = (s == l);
        if (z_) Ld = C;
        #pragma unroll
        for (int j = 0; j < 8; ++j) if (z_) B[j] = C;

        // ---- 8x8 block; scores LDS'd per column-half from ring slot ----
        float dc_ = Ld, ymx_ = 0.f;
        const int slot = s & 3;
        #pragma unroll
        for (int h = 0; h < 2; ++h) {
            float4 sq[8];
            #pragma unroll
            for (int j = 0; j < 8; ++j) sq[j] = stile[slot][2 * j + h][l];
            #pragma unroll
            for (int c2 = 0; c2 < 4; ++c2) {
                const int cc = 4 * h + c2;
                float u_ = B[cc];
                float es0 = ex2f(((const float*)&sq[0])[c2] * LOG2E);
                float es1 = ex2f(((const float*)&sq[1])[c2] * LOG2E);
                float es2 = ex2f(((const float*)&sq[2])[c2] * LOG2E);
                float es3 = ex2f(((const float*)&sq[3])[c2] * LOG2E);
                float es4 = ex2f(((const float*)&sq[4])[c2] * LOG2E);
                float es5 = ex2f(((const float*)&sq[5])[c2] * LOG2E);
                float es6 = ex2f(((const float*)&sq[6])[c2] * LOG2E);
                float es7 = ex2f(((const float*)&sq[7])[c2] * LOG2E);
                float v0 = fmaf(EG, Lf[0], fmaf(EG, u_, fmaf(es0, dc_,   C)));
                float v1 = fmaf(EG, Lf[1], fmaf(EG, v0, fmaf(es1, Lf[0], C)));
                float v2 = fmaf(EG, Lf[2], fmaf(EG, v1, fmaf(es2, Lf[1], C)));
                float v3 = fmaf(EG, Lf[3], fmaf(EG, v2, fmaf(es3, Lf[2], C)));
                float v4 = fmaf(EG, Lf[4], fmaf(EG, v3, fmaf(es4, Lf[3], C)));
                float v5 = fmaf(EG, Lf[5], fmaf(EG, v4, fmaf(es5, Lf[4], C)));
                float v6 = fmaf(EG, Lf[6], fmaf(EG, v5, fmaf(es6, Lf[5], C)));
                float v7 = fmaf(EG, Lf[7], fmaf(EG, v6, fmaf(es7, Lf[6], C)));
                dc_ = u_;
                B[cc] = valid_ ? v7 : u_;
                ymx_ = fmaxf(ymx_, fmaxf(fmaxf(fmaxf(v0, v1), fmaxf(v2, v3)),
                                         fmaxf(fmaxf(v4, v5), fmaxf(v6, v7))));
                Lf[0] = v0; Lf[1] = v1; Lf[2] = v2; Lf[3] = v3;
                Lf[4] = v4; Lf[5] = v5; Lf[6] = v6; Lf[7] = v7;
            }
        }
        Ymax = fmaxf(Ymax, valid_ ? ymx_ : 0.f);
        { float t7_ = yR[7];
          #pragma unroll
          for (int j = 0; j < 8; ++j) yR[j] = valid_ ? Lf[j] : yR[j];
          y7p = valid_ ? t7_ : y7p; }

        // ---- publish right-column rows (lane 31) with own K ----
        if (l == 31 && produce && valid_) {
            float kf_ = __int_as_float(Ki);
            float4* op_ = (float4*)(myedge2 + RB * (s - 31));
            op_[0] = make_float4(Lf[0], kf_, Lf[1], kf_);
            op_[1] = make_float4(Lf[2], kf_, Lf[3], kf_);
            op_[2] = make_float4(Lf[4], kf_, Lf[5], kf_);
            op_[3] = make_float4(Lf[6], kf_, Lf[7], kf_);
            st_rel(myflag, s - 30);
        }
    }

    // ---- final flush + warp reduce + publish (H >= 0) ----
    vh = fmaxf(vh, lg2f(Ymax) + (float)Ki);
    float hv = vh * LN2;
    #pragma unroll
    for (int o = 16; o; o >>= 1)
        hv = fmaxf(hv, __shfl_xor_sync(0xffffffffu, hv, o));
    if (l == 0) atomicMax(&g_max[b], __float_as_int(fmaxf(hv, 0.f)));
#undef ISSUE_SLOT
}

__global__ void sw_final_kernel(float* __restrict__ out, int n) {
    int i = threadIdx.x;
    if (i < n) out[i] = __int_as_float(g_max[i]);
}

extern "C" void kernel_launch(void* const* d_in, const int* in_sizes, int n_in,
                              void* d_out, int out_size) {
    (void)n_in; (void)in_sizes;
    const float* S = (const float*)d_in[0];
    float* out = (float*)d_out;
    const int B = out_size;   // 8

    sw_init_kernel<<<1, 128>>>();
    dim3 grid(NB, 8);
    sw_wave_kernel<<<grid, 32>>>(S);
    sw_final_kernel<<<1, 32>>>(out, B);
}

// round 15
// speedup vs baseline: 1.0444x; 1.0401x over previous
#include <cuda_runtime.h>
#include <cstdint>

// Soft Smith-Waterman, linear (exp) domain, 8x16 row-blocked wavefront,
// per-lane exponent renorm, ACQUIRE/RELEASE edge protocol (R8-proven
// semantics) with BATCHED intake: one acquire + one 32-row edge read per
// 4 steps (Ki is constant between renorms, which sit on 4-step boundaries).
// X = exp(H):  X = 1 + e^s * Xdiag + e^-1 * (Xup + Xleft)
// Lane l owns cols 16l..16l+15 of its 512-col band; computes 8 rows x 16 cols
// per step, staggered 1 step/lane. 4 bands x 8 batches = 32 warps.

#define MM 2048
#define NN 2048
#define RB 8
#define BANDW 512
#define NB 4
#define NSTEP 287
#define SLACK 16
#define LN2   0.6931471805599453f
#define LOG2E 1.4426950408889634f
#define EG    0.36787944117144233f    // e^-1

__device__ float g_edgeY[8][NB][MM];        // edge Y per row
__device__ int   g_edgeK[8][NB][MM / RB];   // edge K per 8-row group
__device__ int   g_flag[8][NB];
__device__ int   g_max[8];

static __device__ __forceinline__ float ex2f(float x) {
    float r; asm("ex2.approx.f32 %0, %1;" : "=f"(r) : "f"(x)); return r;
}
static __device__ __forceinline__ float lg2f(float x) {
    float r; asm("lg2.approx.f32 %0, %1;" : "=f"(r) : "f"(x)); return r;
}
static __device__ __forceinline__ int ld_acq(const int* p) {
    int v; asm volatile("ld.global.acquire.gpu.b32 %0, [%1];" : "=r"(v) : "l"(p)); return v;
}
static __device__ __forceinline__ void st_rel(int* p, int v) {
    asm volatile("st.global.release.gpu.b32 [%0], %1;" :: "l"(p), "r"(v) : "memory");
}
static __device__ __forceinline__ float4 ldcg4(const float4* p) {
    float4 v;
    asm volatile("ld.global.cg.v4.f32 {%0,%1,%2,%3}, [%4];"
                 : "=f"(v.x), "=f"(v.y), "=f"(v.z), "=f"(v.w) : "l"(p));
    return v;
}
static __device__ __forceinline__ int4 ldcg4i(const int4* p) {
    int4 v;
    asm volatile("ld.global.cg.v4.b32 {%0,%1,%2,%3}, [%4];"
                 : "=r"(v.x), "=r"(v.y), "=r"(v.z), "=r"(v.w) : "l"(p));
    return v;
}
static __device__ __forceinline__ void stcg4(float4* p, float4 v) {
    asm volatile("st.global.cg.v4.f32 [%0], {%1,%2,%3,%4};"
                 :: "l"(p), "f"(v.x), "f"(v.y), "f"(v.z), "f"(v.w) : "memory");
}
static __device__ __forceinline__ void stcg_i(int* p, int v) {
    asm volatile("st.global.cg.b32 [%0], %1;" :: "l"(p), "r"(v) : "memory");
}
static __device__ __forceinline__ void cp16(uint32_t dst, const void* src) {
    asm volatile("cp.async.cg.shared.global [%0], [%1], 16;" :: "r"(dst), "l"(src));
}
static __device__ __forceinline__ void cp_commit() {
    asm volatile("cp.async.commit_group;" ::: "memory");
}
template <int N> static __device__ __forceinline__ void cp_wait() {
    asm volatile("cp.async.wait_group %0;" :: "n"(N) : "memory");
}
static __device__ __forceinline__ float pow2i(int k) {   // 2^k, k in [-126,127]
    return __int_as_float((127 + k) << 23);
}

__global__ void sw_init_kernel() {
    int i = threadIdx.x;
    if (i < 8 * NB) ((int*)g_flag)[i] = 0;
    if (i < 8) g_max[i] = 0;    // bits of 0.0f; H >= 0
}

__global__ void __launch_bounds__(32, 1) sw_wave_kernel(const float* __restrict__ S) {
    __shared__ float4 stile[3][8][4][32];       // 48 KB ring of raw scores

    const int b = blockIdx.y;
    const int w = blockIdx.x;
    const int l = threadIdx.x;
    const float* Sl = S + (size_t)b * MM * NN + (size_t)w * BANDW + (size_t)l * 16;

    const int*   flagp   = (w > 0) ? &g_flag[b][w - 1]  : (const int*)0;
    const float* edgeYp  = (w > 0) ? g_edgeY[b][w - 1]  : (const float*)0;
    const int*   edgeKp  = (w > 0) ? g_edgeK[b][w - 1]  : (const int*)0;
    float*       myedgeY = g_edgeY[b][w];
    int*         myedgeK = g_edgeK[b][w];
    int*         myflag  = &g_flag[b][w];
    const bool   produce = (w != NB - 1);
    const uint32_t smem_u32 = (uint32_t)__cvta_generic_to_shared(&stile[0][0][0][0]);

    float B[16];
    #pragma unroll
    for (int j = 0; j < 16; ++j) B[j] = 1.f;
    float yR[8];
    #pragma unroll
    for (int j = 0; j < 8; ++j) yR[j] = 1.f;
    float y7p = 1.f, ecarry = 1.f, C = 1.f;
    float Ymax = 0.f, vh = 0.f;
    int   Ki = 0;
    int   flag_seen = 0;
    float4 YQ[8];
    int4   K4 = {0, 0, 0, 0};

#define ISSUE_SLOT(SS, SLOT) { \
    int r0_ = RB * ((SS) - l); \
    r0_ = max(0, min(MM - RB, r0_)); \
    const float* src_ = Sl + (size_t)r0_ * NN; \
    _Pragma("unroll") for (int rr = 0; rr < 8; ++rr) { \
        uint32_t d_ = smem_u32 + ((((SLOT) * 8 + rr) * 4) * 32 + l) * 16; \
        const float* sr_ = src_ + (size_t)rr * NN; \
        cp16(d_, sr_);            cp16(d_ + 512,  sr_ + 4); \
        cp16(d_ + 1024, sr_ + 8); cp16(d_ + 1536, sr_ + 12); } \
    cp_commit(); }

    ISSUE_SLOT(0, 0)
    ISSUE_SLOT(1, 1)

    // Startup slack so steady-state batch acquires return immediately.
    if (w > 0) { while (flag_seen < SLACK) flag_seen = ld_acq(flagp); }

    int sl_cur = 0, sl_iss = 2;
    for (int sb = 0; sb < NSTEP; sb += 4) {
        // ---- per-lane renorm every 4 steps (32 rows) ----
        if (sb != 0) {
            float m_ = B[0];
            #pragma unroll
            for (int j = 1; j < 16; ++j) m_ = fmaxf(m_, B[j]);
            int k_ = (__float_as_int(m_) >> 23) - 127;    // m_ > 0 always
            float sc_ = pow2i(-k_);
            vh = fmaxf(vh, lg2f(Ymax) + (float)Ki);
            Ymax = 0.f; Ki += k_; C *= sc_;
            #pragma unroll
            for (int j = 0; j < 16; ++j) B[j] *= sc_;
            #pragma unroll
            for (int j = 0; j < 8; ++j) yR[j] *= sc_;
            y7p *= sc_; ecarry *= sc_;
        }

        // ---- batched edge intake: one acquire + 32 rows per 4 steps ----
        const bool eb = (w > 0) && (sb < 256);
        if (eb) {
            const int need = sb + 4;    // groups sb..sb+3 published
            while (flag_seen < need) flag_seen = ld_acq(flagp);
            const float4* yp = (const float4*)(edgeYp + RB * sb);
            #pragma unroll
            for (int q = 0; q < 8; ++q) YQ[q] = ldcg4(yp + q);
            K4 = ldcg4i((const int4*)(edgeKp + sb));
        }

        #pragma unroll
        for (int j = 0; j < 4; ++j) {
            const int s = sb + j;
            if (s >= NSTEP) break;

            // ---- score pipeline: issue slot s+2, ensure slot s resident ----
            ISSUE_SLOT(s + 2, sl_iss)
            cp_wait<2>();

            // ---- edge conversion for this step (Ki constant in batch) ----
            float e_[8];
            if (eb) {
                const int kj = (j == 0) ? K4.x : (j == 1) ? K4.y
                             : (j == 2) ? K4.z : K4.w;
                const float fs = pow2i(max(-126, min(127, kj - Ki)));
                float4 ya = YQ[2 * j], yb = YQ[2 * j + 1];
                e_[0] = ya.x * fs; e_[1] = ya.y * fs;
                e_[2] = ya.z * fs; e_[3] = ya.w * fs;
                e_[4] = yb.x * fs; e_[5] = yb.y * fs;
                e_[6] = yb.z * fs; e_[7] = yb.w * fs;
            } else {
                #pragma unroll
                for (int t = 0; t < 8; ++t) e_[t] = C;
            }

            // ---- neighbor exchange with per-lane rescale 2^(K[l-1]-K[l]) ----
            int kk_ = __shfl_up_sync(0xffffffffu, Ki, 1);
            float fs_ = pow2i(max(-126, min(127, kk_ - Ki)));
            float Lf[8]; float Ld;
            #pragma unroll
            for (int t = 0; t < 8; ++t) {
                float tv = __shfl_up_sync(0xffffffffu, yR[t], 1);
                Lf[t] = (l == 0) ? e_[t] : tv * fs_;
            }
            { float tv = __shfl_up_sync(0xffffffffu, y7p, 1);
              Ld = (l == 0) ? ecarry : tv * fs_; }
            ecarry = e_[7];

            const bool valid_ = (s >= l) && (s - l < 256);
            const bool z_ = (s == l);
            if (z_) Ld = C;
            #pragma unroll
            for (int t = 0; t < 16; ++t) if (z_) B[t] = C;

            // ---- 8x16 block, in-loop ex2 ----
            float dc_ = Ld, ymx_ = 0.f;
            #pragma unroll
            for (int h = 0; h < 4; ++h) {
                float4 sq[8];
                #pragma unroll
                for (int t = 0; t < 8; ++t) sq[t] = stile[sl_cur][t][h][l];
                #pragma unroll
                for (int c2 = 0; c2 < 4; ++c2) {
                    const int cc = 4 * h + c2;
                    float u_ = B[cc];
                    float es0 = ex2f(((const float*)&sq[0])[c2] * LOG2E);
                    float es1 = ex2f(((const float*)&sq[1])[c2] * LOG2E);
                    float es2 = ex2f(((const float*)&sq[2])[c2] * LOG2E);
                    float es3 = ex2f(((const float*)&sq[3])[c2] * LOG2E);
                    float es4 = ex2f(((const float*)&sq[4])[c2] * LOG2E);
                    float es5 = ex2f(((const float*)&sq[5])[c2] * LOG2E);
                    float es6 = ex2f(((const float*)&sq[6])[c2] * LOG2E);
                    float es7 = ex2f(((const float*)&sq[7])[c2] * LOG2E);
                    float v0 = fmaf(EG, Lf[0], fmaf(EG, u_, fmaf(es0, dc_,   C)));
                    float v1 = fmaf(EG, Lf[1], fmaf(EG, v0, fmaf(es1, Lf[0], C)));
                    float v2 = fmaf(EG, Lf[2], fmaf(EG, v1, fmaf(es2, Lf[1], C)));
                    float v3 = fmaf(EG, Lf[3], fmaf(EG, v2, fmaf(es3, Lf[2], C)));
                    float v4 = fmaf(EG, Lf[4], fmaf(EG, v3, fmaf(es4, Lf[3], C)));
                    float v5 = fmaf(EG, Lf[5], fmaf(EG, v4, fmaf(es5, Lf[4], C)));
                    float v6 = fmaf(EG, Lf[6], fmaf(EG, v5, fmaf(es6, Lf[5], C)));
                    float v7 = fmaf(EG, Lf[7], fmaf(EG, v6, fmaf(es7, Lf[6], C)));
                    dc_ = u_;
                    B[cc] = valid_ ? v7 : u_;
                    ymx_ = fmaxf(ymx_, fmaxf(fmaxf(fmaxf(v0, v1), fmaxf(v2, v3)),
                                             fmaxf(fmaxf(v4, v5), fmaxf(v6, v7))));
                    Lf[0] = v0; Lf[1] = v1; Lf[2] = v2; Lf[3] = v3;
                    Lf[4] = v4; Lf[5] = v5; Lf[6] = v6; Lf[7] = v7;
                }
            }
            Ymax = fmaxf(Ymax, valid_ ? ymx_ : 0.f);
            { float t7_ = yR[7];
              #pragma unroll
              for (int t = 0; t < 8; ++t) yR[t] = valid_ ? Lf[t] : yR[t];
              y7p = valid_ ? t7_ : y7p; }

            // ---- publish right-column rows (Y) + group K + release flag ----
            if (l == 31 && produce && valid_) {
                const int r0 = RB * (s - 31);
                float4* yp = (float4*)(myedgeY + r0);
                stcg4(yp,     make_float4(Lf[0], Lf[1], Lf[2], Lf[3]));
                stcg4(yp + 1, make_float4(Lf[4], Lf[5], Lf[6], Lf[7]));
                stcg_i(myedgeK + (r0 >> 3), Ki);
                st_rel(myflag, s - 30);
            }

            sl_cur = (sl_cur == 2) ? 0 : sl_cur + 1;
            sl_iss = (sl_iss == 2) ? 0 : sl_iss + 1;
        }
    }

    // ---- final flush + warp reduce + publish (H >= 0) ----
    vh = fmaxf(vh, lg2f(Ymax) + (float)Ki);
    float hv = vh * LN2;
    #pragma unroll
    for (int o = 16; o; o >>= 1)
        hv = fmaxf(hv, __shfl_xor_sync(0xffffffffu, hv, o));
    if (l == 0) atomicMax(&g_max[b], __float_as_int(fmaxf(hv, 0.f)));
#undef ISSUE_SLOT
}

__global__ void sw_final_kernel(float* __restrict__ out, int n) {
    int i = threadIdx.x;
    if (i < n) out[i] = __int_as_float(g_max[i]);
}

extern "C" void kernel_launch(void* const* d_in, const int* in_sizes, int n_in,
                              void* d_out, int out_size) {
    (void)n_in; (void)in_sizes;
    const float* S = (const float*)d_in[0];
    float* out = (float*)d_out;
    const int B = out_size;   // 8

    sw_init_kernel<<<1, 64>>>();
    dim3 grid(NB, 8);
    sw_wave_kernel<<<grid, 32>>>(S);
    sw_final_kernel<<<1, 32>>>(out, B);
}